// round 5
// baseline (speedup 1.0000x reference)
#include <cuda_runtime.h>
#include <float.h>

#define NB 32
#define NS 512
#define NH 1024
#define NCAND 256
#define NL 34
#define NCH 16      // chunks per sequence
#define CSZ 32      // tokens per chunk
#define SPLIT 4     // K-split for gemm
#define CPB 4       // candidates per gemm block
#define KS (2 * NH / SPLIT)   // 512

// Scratch (__device__ globals; no allocation allowed)
__device__ float g_cmax[NB * NCH * NH];          // chunk maxes
__device__ float g_plp[NCAND * NH];              // candidate in-chunk left partial
__device__ float g_prp[NCAND * NH];              // candidate in-chunk right partial
__device__ float g_pooled[NCAND * 2 * NH];
__device__ float g_Wt[NL * 2 * NH];              // W transposed [34][2048]
__device__ float g_part[SPLIT * NCAND * NL];     // gemm partials

// ---------------------------------------------------------------------------
// Phase A (fused): chunkmax[b,q,h] = max over 32 tokens, AND for every
// candidate whose cut falls inside this chunk, the in-chunk left/right
// partial maxes — computed from the same register-resident token values.
// hidden is read exactly once (64 MB) across the whole pipeline.
// ---------------------------------------------------------------------------
__global__ void k_chunkmax(const float* __restrict__ hidden,
                           const int* __restrict__ cb,
                           const int* __restrict__ cc) {
    __shared__ int s_cnt;
    __shared__ int s_n[NCAND];
    __shared__ int s_r[NCAND];

    int tid = threadIdx.x;
    int h = blockIdx.x * 256 + tid;
    int q = blockIdx.y;
    int b = blockIdx.z;

    if (tid == 0) s_cnt = 0;
    __syncthreads();
    if (tid < NCAND) {
        int cn = cc[tid];
        if (cb[tid] == b && (cn >> 5) == q) {
            int p = atomicAdd(&s_cnt, 1);
            s_n[p] = tid;
            s_r[p] = cn & 31;
        }
    }

    const float* base = hidden + ((size_t)(b * NS + q * CSZ)) * NH + h;
    float v[CSZ];
#pragma unroll
    for (int k = 0; k < CSZ; k++) v[k] = base[(size_t)k * NH];
    float m = -FLT_MAX;
#pragma unroll
    for (int k = 0; k < CSZ; k++) m = fmaxf(m, v[k]);
    g_cmax[((size_t)b * NCH + q) * NH + h] = m;

    __syncthreads();
    int cnt = s_cnt;
    for (int j = 0; j < cnt; j++) {
        int n = s_n[j];
        int r = s_r[j];
        float ml = -FLT_MAX, mr = -FLT_MAX;
#pragma unroll
        for (int k = 0; k < CSZ; k++) {
            if (k < r) ml = fmaxf(ml, v[k]);
            else       mr = fmaxf(mr, v[k]);
        }
        g_plp[(size_t)n * NH + h] = ml;
        g_prp[(size_t)n * NH + h] = mr;
    }
}

// ---------------------------------------------------------------------------
// Phase B (fused): per (b, h-tile) prefix/suffix max over the 16 chunk
// values (kept in shared), then directly emit pooled vectors for every
// candidate of batch b:  pooledL = max(plp, pref[q]),
//                        pooledR = max(prp, suf[q+1]).
// ---------------------------------------------------------------------------
__global__ void k_scan_combine(const int* __restrict__ cb,
                               const int* __restrict__ cc) {
    __shared__ float sh_pref[NCH][256];   // pref[q] = max chunks < q
    __shared__ float sh_suf[NCH][256];    // sh_suf[q] = max chunks > q  (= suf[q+1])
    __shared__ int s_cnt;
    __shared__ int s_n[NCAND];
    __shared__ int s_q[NCAND];

    int tid = threadIdx.x;
    int h = blockIdx.x * 256 + tid;
    int b = blockIdx.y;

    if (tid == 0) s_cnt = 0;
    __syncthreads();
    if (tid < NCAND) {
        if (cb[tid] == b) {
            int p = atomicAdd(&s_cnt, 1);
            s_n[p] = tid;
            s_q[p] = cc[tid] >> 5;
        }
    }

    const float* cm = g_cmax + (size_t)b * NCH * NH + h;
    float v[NCH];
#pragma unroll
    for (int q = 0; q < NCH; q++) v[q] = cm[(size_t)q * NH];

    float run = -FLT_MAX;
#pragma unroll
    for (int q = 0; q < NCH; q++) {
        sh_pref[q][tid] = run;
        run = fmaxf(run, v[q]);
    }
    run = -FLT_MAX;
#pragma unroll
    for (int q = NCH - 1; q >= 0; q--) {
        sh_suf[q][tid] = run;
        run = fmaxf(run, v[q]);
    }
    __syncthreads();

    int cnt = s_cnt;
    for (int j = 0; j < cnt; j++) {
        int n = s_n[j];
        int q = s_q[j];
        float pl = fmaxf(g_plp[(size_t)n * NH + h], sh_pref[q][tid]);
        float pr = fmaxf(g_prp[(size_t)n * NH + h], sh_suf[q][tid]);
        g_pooled[(size_t)n * (2 * NH) + h] = pl;
        g_pooled[(size_t)n * (2 * NH) + NH + h] = pr;
    }
}

// ---------------------------------------------------------------------------
// Phase D0: transpose W [2048,34] -> Wt [34,2048] so gemm loads coalesce.
// ---------------------------------------------------------------------------
__global__ void k_wt(const float* __restrict__ W) {
    int idx = blockIdx.x * 1024 + threadIdx.x;
    if (idx < NL * 2 * NH) {
        int l = idx >> 11;
        int k = idx & (2 * NH - 1);
        g_Wt[idx] = W[(size_t)k * NL + l];
    }
}

// ---------------------------------------------------------------------------
// Phase D1: warp-per-(cand,label) dot, K split in 4 quarters. 4096 warps,
// all lanes live, float4 on both operands (4 independent pairs per lane).
// ---------------------------------------------------------------------------
__global__ void k_gemm() {
    int wid = threadIdx.x >> 5;
    int lane = threadIdx.x & 31;
    int kbase = blockIdx.y * KS;

#pragma unroll 1
    for (int d = wid; d < CPB * NL; d += 16) {
        int c = d / NL;
        int l = d - c * NL;
        int cand = blockIdx.x * CPB + c;
        const float4* a = (const float4*)(g_pooled + (size_t)cand * (2 * NH) + kbase);
        const float4* w = (const float4*)(g_Wt + (size_t)l * (2 * NH) + kbase);
        float s0 = 0.f, s1 = 0.f, s2 = 0.f, s3 = 0.f;
#pragma unroll
        for (int i = 0; i < KS / 128; i++) {
            float4 av = a[lane + i * 32];
            float4 wv = w[lane + i * 32];
            s0 += av.x * wv.x;
            s1 += av.y * wv.y;
            s2 += av.z * wv.z;
            s3 += av.w * wv.w;
        }
        float s = (s0 + s1) + (s2 + s3);
#pragma unroll
        for (int o = 16; o; o >>= 1) s += __shfl_xor_sync(0xffffffffu, s, o);
        if (lane == 0)
            g_part[((size_t)blockIdx.y * NCAND + cand) * NL + l] = s;
    }
}

// ---------------------------------------------------------------------------
// Phase D2: sum the 4 K-partials + bias (deterministic).
// ---------------------------------------------------------------------------
__global__ void k_red(const float* __restrict__ bias, float* __restrict__ out) {
    int i = blockIdx.x * 256 + threadIdx.x;
    if (i < NCAND * NL) {
        int l = i % NL;
        float s = bias[l];
#pragma unroll
        for (int p = 0; p < SPLIT; p++) s += g_part[p * NCAND * NL + i];
        out[i] = s;
    }
}

// ---------------------------------------------------------------------------
extern "C" void kernel_launch(void* const* d_in, const int* in_sizes, int n_in,
                              void* d_out, int out_size) {
    const float* hidden = (const float*)d_in[0];
    const float* W = (const float*)d_in[1];
    const float* bias = (const float*)d_in[2];
    const int* cb = (const int*)d_in[3];
    const int* cc = (const int*)d_in[4];
    float* out = (float*)d_out;

    k_wt<<<(NL * 2 * NH + 1023) / 1024, 1024>>>(W);

    dim3 gA(NH / 256, NCH, NB);
    k_chunkmax<<<gA, 256>>>(hidden, cb, cc);

    dim3 gB(NH / 256, NB);
    k_scan_combine<<<gB, 256>>>(cb, cc);

    dim3 gD(NCAND / CPB, SPLIT);
    k_gemm<<<gD, 512>>>();

    k_red<<<(NCAND * NL + 255) / 256, 256>>>(bias, out);
}

// round 6
// speedup vs baseline: 1.1603x; 1.1603x over previous
#include <cuda_runtime.h>
#include <float.h>

#define NB 32
#define NS 512
#define NH 1024
#define NCAND 256
#define NL 34
#define NLP 36      // labels padded to 9 quads
#define NCH 16      // chunks per sequence
#define CSZ 32      // tokens per chunk
#define SPLIT 8     // K-split for gemm (KS = 256)
#define KS (2 * NH / SPLIT)

// Scratch (__device__ globals; no allocation allowed)
__device__ float g_cmax[NB * NCH * NH];          // chunk maxes
__device__ float g_plp[NCAND * NH];              // candidate in-chunk left partial
__device__ float g_prp[NCAND * NH];              // candidate in-chunk right partial
__device__ float g_pooled[NCAND * 2 * NH];
__device__ float g_Wt[NLP * 2 * NH];             // W transposed+padded [36][2048]
__device__ float g_part[SPLIT * NCAND * NLP];    // gemm partials

// ---------------------------------------------------------------------------
// Phase A (fused): chunkmax[b,q,h] = max over 32 tokens, plus in-chunk
// left/right partial maxes for candidates whose cut lands in this chunk
// (computed from the register-resident token values). hidden read once.
// ---------------------------------------------------------------------------
__global__ void k_chunkmax(const float* __restrict__ hidden,
                           const int* __restrict__ cb,
                           const int* __restrict__ cc) {
    __shared__ int s_cnt;
    __shared__ int s_n[NCAND];
    __shared__ int s_r[NCAND];

    int tid = threadIdx.x;
    int h = blockIdx.x * 256 + tid;
    int q = blockIdx.y;
    int b = blockIdx.z;

    if (tid == 0) s_cnt = 0;
    __syncthreads();
    if (tid < NCAND) {
        int cn = cc[tid];
        if (cb[tid] == b && (cn >> 5) == q) {
            int p = atomicAdd(&s_cnt, 1);
            s_n[p] = tid;
            s_r[p] = cn & 31;
        }
    }

    const float* base = hidden + ((size_t)(b * NS + q * CSZ)) * NH + h;
    float v[CSZ];
#pragma unroll
    for (int k = 0; k < CSZ; k++) v[k] = base[(size_t)k * NH];
    float m = -FLT_MAX;
#pragma unroll
    for (int k = 0; k < CSZ; k++) m = fmaxf(m, v[k]);
    g_cmax[((size_t)b * NCH + q) * NH + h] = m;

    __syncthreads();
    int cnt = s_cnt;
    for (int j = 0; j < cnt; j++) {
        int n = s_n[j];
        int r = s_r[j];
        float ml = -FLT_MAX, mr = -FLT_MAX;
#pragma unroll
        for (int k = 0; k < CSZ; k++) {
            if (k < r) ml = fmaxf(ml, v[k]);
            else       mr = fmaxf(mr, v[k]);
        }
        g_plp[(size_t)n * NH + h] = ml;
        g_prp[(size_t)n * NH + h] = mr;
    }
}

// ---------------------------------------------------------------------------
// Phase B (fused): prefix/suffix max over chunk maxes (shared), then emit
// pooled vectors for every candidate of batch b.
// ---------------------------------------------------------------------------
__global__ void k_scan_combine(const int* __restrict__ cb,
                               const int* __restrict__ cc) {
    __shared__ float sh_pref[NCH][256];   // pref[q] = max chunks < q
    __shared__ float sh_suf[NCH][256];    // sh_suf[q] = max chunks > q
    __shared__ int s_cnt;
    __shared__ int s_n[NCAND];
    __shared__ int s_q[NCAND];

    int tid = threadIdx.x;
    int h = blockIdx.x * 256 + tid;
    int b = blockIdx.y;

    if (tid == 0) s_cnt = 0;
    __syncthreads();
    if (tid < NCAND) {
        if (cb[tid] == b) {
            int p = atomicAdd(&s_cnt, 1);
            s_n[p] = tid;
            s_q[p] = cc[tid] >> 5;
        }
    }

    const float* cm = g_cmax + (size_t)b * NCH * NH + h;
    float v[NCH];
#pragma unroll
    for (int q = 0; q < NCH; q++) v[q] = cm[(size_t)q * NH];

    float run = -FLT_MAX;
#pragma unroll
    for (int q = 0; q < NCH; q++) {
        sh_pref[q][tid] = run;
        run = fmaxf(run, v[q]);
    }
    run = -FLT_MAX;
#pragma unroll
    for (int q = NCH - 1; q >= 0; q--) {
        sh_suf[q][tid] = run;
        run = fmaxf(run, v[q]);
    }
    __syncthreads();

    int cnt = s_cnt;
    for (int j = 0; j < cnt; j++) {
        int n = s_n[j];
        int q = s_q[j];
        float pl = fmaxf(g_plp[(size_t)n * NH + h], sh_pref[q][tid]);
        float pr = fmaxf(g_prp[(size_t)n * NH + h], sh_suf[q][tid]);
        g_pooled[(size_t)n * (2 * NH) + h] = pl;
        g_pooled[(size_t)n * (2 * NH) + NH + h] = pr;
    }
}

// ---------------------------------------------------------------------------
// Phase D0: transpose W [2048,34] -> Wt [36,2048] (rows 34,35 zero).
// ---------------------------------------------------------------------------
__global__ void k_wt(const float* __restrict__ W) {
    int idx = blockIdx.x * 1024 + threadIdx.x;
    if (idx < NLP * 2 * NH) {
        int l = idx >> 11;
        int k = idx & (2 * NH - 1);
        g_Wt[idx] = (l < NL) ? W[(size_t)k * NL + l] : 0.f;
    }
}

// ---------------------------------------------------------------------------
// Phase D1: register-tiled gemm. Warp = (cand-quad, label-quad, K-eighth).
// Lane owns a K-strip (2 float4 steps); holds 4 A-float4 + 4 W-float4 and
// does 64 FMA per 8 loads (2 B/FMA -> ~35 MB total LSU traffic vs 142 MB
// for warp-per-dot). Block's 8 warps share the same 4 A + 4 W rows.
// Grid 576 blocks x 256 thr, perfectly balanced.
// ---------------------------------------------------------------------------
__global__ void k_gemm() {
    int wid = threadIdx.x >> 5;     // K-split 0..7
    int lane = threadIdx.x & 31;
    int t = blockIdx.x;             // 0..575
    int cq = t / 9;                 // cand-quad 0..63
    int lq = t - cq * 9;            // label-quad 0..8
    int kbase = wid * KS;

    const float4* A0 = (const float4*)(g_pooled + (size_t)(cq * 4 + 0) * (2 * NH) + kbase);
    const float4* A1 = (const float4*)(g_pooled + (size_t)(cq * 4 + 1) * (2 * NH) + kbase);
    const float4* A2 = (const float4*)(g_pooled + (size_t)(cq * 4 + 2) * (2 * NH) + kbase);
    const float4* A3 = (const float4*)(g_pooled + (size_t)(cq * 4 + 3) * (2 * NH) + kbase);
    const float4* W0 = (const float4*)(g_Wt + (size_t)(lq * 4 + 0) * (2 * NH) + kbase);
    const float4* W1 = (const float4*)(g_Wt + (size_t)(lq * 4 + 1) * (2 * NH) + kbase);
    const float4* W2 = (const float4*)(g_Wt + (size_t)(lq * 4 + 2) * (2 * NH) + kbase);
    const float4* W3 = (const float4*)(g_Wt + (size_t)(lq * 4 + 3) * (2 * NH) + kbase);

    float acc[4][4];
#pragma unroll
    for (int c = 0; c < 4; c++)
#pragma unroll
        for (int l = 0; l < 4; l++) acc[c][l] = 0.f;

#pragma unroll
    for (int step = 0; step < KS / 128; step++) {   // 2 steps
        int i = lane + step * 32;
        float4 a[4], w[4];
        a[0] = A0[i]; a[1] = A1[i]; a[2] = A2[i]; a[3] = A3[i];
        w[0] = W0[i]; w[1] = W1[i]; w[2] = W2[i]; w[3] = W3[i];
#pragma unroll
        for (int c = 0; c < 4; c++)
#pragma unroll
            for (int l = 0; l < 4; l++) {
                acc[c][l] += a[c].x * w[l].x;
                acc[c][l] += a[c].y * w[l].y;
                acc[c][l] += a[c].z * w[l].z;
                acc[c][l] += a[c].w * w[l].w;
            }
    }

    // Warp-reduce all 16 accumulators (independent chains overlap latency).
#pragma unroll
    for (int c = 0; c < 4; c++)
#pragma unroll
        for (int l = 0; l < 4; l++) {
            float s = acc[c][l];
#pragma unroll
            for (int o = 16; o; o >>= 1) s += __shfl_xor_sync(0xffffffffu, s, o);
            acc[c][l] = s;
        }

    if (lane == 0) {
#pragma unroll
        for (int c = 0; c < 4; c++)
#pragma unroll
            for (int l = 0; l < 4; l++)
                g_part[((size_t)wid * NCAND + cq * 4 + c) * NLP + lq * 4 + l] = acc[c][l];
    }
}

// ---------------------------------------------------------------------------
// Phase D2: sum the 8 K-partials + bias (deterministic).
// ---------------------------------------------------------------------------
__global__ void k_red(const float* __restrict__ bias, float* __restrict__ out) {
    int i = blockIdx.x * 256 + threadIdx.x;
    if (i < NCAND * NL) {
        int cand = i / NL;
        int l = i - cand * NL;
        float s = bias[l];
#pragma unroll
        for (int p = 0; p < SPLIT; p++)
            s += g_part[((size_t)p * NCAND + cand) * NLP + l];
        out[i] = s;
    }
}

// ---------------------------------------------------------------------------
extern "C" void kernel_launch(void* const* d_in, const int* in_sizes, int n_in,
                              void* d_out, int out_size) {
    const float* hidden = (const float*)d_in[0];
    const float* W = (const float*)d_in[1];
    const float* bias = (const float*)d_in[2];
    const int* cb = (const int*)d_in[3];
    const int* cc = (const int*)d_in[4];
    float* out = (float*)d_out;

    k_wt<<<(NLP * 2 * NH + 1023) / 1024, 1024>>>(W);

    dim3 gA(NH / 256, NCH, NB);
    k_chunkmax<<<gA, 256>>>(hidden, cb, cc);

    dim3 gB(NH / 256, NB);
    k_scan_combine<<<gB, 256>>>(cb, cc);

    k_gemm<<<64 * 9, 256>>>();

    k_red<<<(NCAND * NL + 255) / 256, 256>>>(bias, out);
}

// round 7
// speedup vs baseline: 1.2545x; 1.0812x over previous
#include <cuda_runtime.h>
#include <float.h>

#define NB 32
#define NS 512
#define NH 1024
#define NCAND 256
#define NL 34
#define NLP 36      // labels padded to 9 quads
#define NCH 16      // chunks per sequence
#define CSZ 32      // tokens per chunk
#define SPLIT 8     // K-split for gemm
#define KS (2 * NH / SPLIT)   // 256 floats per split
#define CMB 2048    // chunkmax blocks in fused kernel A
#define WTB 288     // wt blocks in fused kernel A (288*256 = 36*2048)

// Scratch (__device__ globals; no allocation allowed)
__device__ float g_cmax[NB * NCH * NH];
__device__ float g_plp[NCAND * NH];
__device__ float g_prp[NCAND * NH];
__device__ float g_pooled[NCAND * 2 * NH];
__device__ float g_Wt[NLP * 2 * NH];             // W transposed+padded [36][2048]
__device__ float g_part[SPLIT * NCAND * NLP];

// ---------------------------------------------------------------------------
// Kernel A (fused): chunk maxes + candidate in-chunk partials, AND the W
// transpose as extra trailing blocks (overlaps with the DRAM-bound stream).
// ---------------------------------------------------------------------------
__global__ void k_A(const float* __restrict__ hidden,
                    const float* __restrict__ W,
                    const int* __restrict__ cb,
                    const int* __restrict__ cc) {
    int bid = blockIdx.x;
    int tid = threadIdx.x;

    if (bid >= CMB) {   // ---- W transpose part ----
        int idx = (bid - CMB) * 256 + tid;
        int l = idx >> 11;
        int k = idx & (2 * NH - 1);
        g_Wt[idx] = (l < NL) ? W[(size_t)k * NL + l] : 0.f;
        return;
    }

    // ---- chunkmax part: bid = b*64 + q*4 + hblk ----
    __shared__ int s_cnt;
    __shared__ int s_n[NCAND];
    __shared__ int s_r[NCAND];

    int b = bid >> 6;
    int rest = bid & 63;
    int q = rest >> 2;
    int h = (rest & 3) * 256 + tid;

    if (tid == 0) s_cnt = 0;
    __syncthreads();
    {
        int cn = cc[tid];           // tid in [0,256) == NCAND
        if (cb[tid] == b && (cn >> 5) == q) {
            int p = atomicAdd(&s_cnt, 1);
            s_n[p] = tid;
            s_r[p] = cn & 31;
        }
    }

    const float* base = hidden + ((size_t)(b * NS + q * CSZ)) * NH + h;
    float v[CSZ];
#pragma unroll
    for (int k = 0; k < CSZ; k++) v[k] = base[(size_t)k * NH];
    float m = -FLT_MAX;
#pragma unroll
    for (int k = 0; k < CSZ; k++) m = fmaxf(m, v[k]);
    g_cmax[((size_t)b * NCH + q) * NH + h] = m;

    __syncthreads();
    int cnt = s_cnt;
    for (int j = 0; j < cnt; j++) {
        int n = s_n[j];
        int r = s_r[j];
        float ml = -FLT_MAX, mr = -FLT_MAX;
#pragma unroll
        for (int k = 0; k < CSZ; k++) {
            if (k < r) ml = fmaxf(ml, v[k]);
            else       mr = fmaxf(mr, v[k]);
        }
        g_plp[(size_t)n * NH + h] = ml;
        g_prp[(size_t)n * NH + h] = mr;
    }
}

// ---------------------------------------------------------------------------
// Kernel B: prefix/suffix max over chunk maxes, emit pooled per candidate.
// ---------------------------------------------------------------------------
__global__ void k_scan_combine(const int* __restrict__ cb,
                               const int* __restrict__ cc) {
    __shared__ float sh_pref[NCH][256];
    __shared__ float sh_suf[NCH][256];
    __shared__ int s_cnt;
    __shared__ int s_n[NCAND];
    __shared__ int s_q[NCAND];

    int tid = threadIdx.x;
    int h = blockIdx.x * 256 + tid;
    int b = blockIdx.y;

    if (tid == 0) s_cnt = 0;
    __syncthreads();
    if (cb[tid] == b) {
        int p = atomicAdd(&s_cnt, 1);
        s_n[p] = tid;
        s_q[p] = cc[tid] >> 5;
    }

    const float* cm = g_cmax + (size_t)b * NCH * NH + h;
    float v[NCH];
#pragma unroll
    for (int q = 0; q < NCH; q++) v[q] = cm[(size_t)q * NH];

    float run = -FLT_MAX;
#pragma unroll
    for (int q = 0; q < NCH; q++) {
        sh_pref[q][tid] = run;
        run = fmaxf(run, v[q]);
    }
    run = -FLT_MAX;
#pragma unroll
    for (int q = NCH - 1; q >= 0; q--) {
        sh_suf[q][tid] = run;
        run = fmaxf(run, v[q]);
    }
    __syncthreads();

    int cnt = s_cnt;
    for (int j = 0; j < cnt; j++) {
        int n = s_n[j];
        int q = s_q[j];
        float pl = fmaxf(g_plp[(size_t)n * NH + h], sh_pref[q][tid]);
        float pr = fmaxf(g_prp[(size_t)n * NH + h], sh_suf[q][tid]);
        g_pooled[(size_t)n * (2 * NH) + h] = pl;
        g_pooled[(size_t)n * (2 * NH) + NH + h] = pr;
    }
}

// ---------------------------------------------------------------------------
// Kernel C: gemm. Block = (cand-oct, K-eighth); 9 warps = 9 label-quads
// sharing the block's 8 A rows via L1. Lane holds 8 A-float4 + 4 W-float4,
// 128 FMA per 12 loads (1.5 B/FMA). L2 traffic: A 2 MB once + W 9.4 MB.
// Grid 32x8 = 256 blocks x 288 thr = 2304 warps.
// ---------------------------------------------------------------------------
__global__ __launch_bounds__(288) void k_gemm() {
    int lq = threadIdx.x >> 5;      // label-quad 0..8
    int lane = threadIdx.x & 31;
    int co = blockIdx.x;            // cand-oct 0..31
    int ks = blockIdx.y;            // K-split 0..7
    int kbase = ks * KS;

    const float4* A = (const float4*)(g_pooled + (size_t)(co * 8) * (2 * NH) + kbase);
    const float4* Wt = (const float4*)(g_Wt + (size_t)(lq * 4) * (2 * NH) + kbase);
    const int rs = (2 * NH) / 4;    // row stride in float4

    float acc[8][4];
#pragma unroll
    for (int c = 0; c < 8; c++)
#pragma unroll
        for (int l = 0; l < 4; l++) acc[c][l] = 0.f;

#pragma unroll
    for (int step = 0; step < KS / 128; step++) {   // 2 steps
        int i = lane + step * 32;
        float4 a[8], w[4];
#pragma unroll
        for (int c = 0; c < 8; c++) a[c] = A[c * rs + i];
#pragma unroll
        for (int l = 0; l < 4; l++) w[l] = Wt[l * rs + i];
#pragma unroll
        for (int c = 0; c < 8; c++)
#pragma unroll
            for (int l = 0; l < 4; l++) {
                acc[c][l] += a[c].x * w[l].x;
                acc[c][l] += a[c].y * w[l].y;
                acc[c][l] += a[c].z * w[l].z;
                acc[c][l] += a[c].w * w[l].w;
            }
    }

#pragma unroll
    for (int c = 0; c < 8; c++)
#pragma unroll
        for (int l = 0; l < 4; l++) {
            float s = acc[c][l];
#pragma unroll
            for (int o = 16; o; o >>= 1) s += __shfl_xor_sync(0xffffffffu, s, o);
            acc[c][l] = s;
        }

    if (lane == 0) {
#pragma unroll
        for (int c = 0; c < 8; c++)
#pragma unroll
            for (int l = 0; l < 4; l++)
                g_part[((size_t)ks * NCAND + co * 8 + c) * NLP + lq * 4 + l] = acc[c][l];
    }
}

// ---------------------------------------------------------------------------
// Kernel D: sum the 8 K-partials + bias (deterministic).
// ---------------------------------------------------------------------------
__global__ void k_red(const float* __restrict__ bias, float* __restrict__ out) {
    int i = blockIdx.x * 256 + threadIdx.x;
    if (i < NCAND * NL) {
        int cand = i / NL;
        int l = i - cand * NL;
        float s = bias[l];
#pragma unroll
        for (int p = 0; p < SPLIT; p++)
            s += g_part[((size_t)p * NCAND + cand) * NLP + l];
        out[i] = s;
    }
}

// ---------------------------------------------------------------------------
extern "C" void kernel_launch(void* const* d_in, const int* in_sizes, int n_in,
                              void* d_out, int out_size) {
    const float* hidden = (const float*)d_in[0];
    const float* W = (const float*)d_in[1];
    const float* bias = (const float*)d_in[2];
    const int* cb = (const int*)d_in[3];
    const int* cc = (const int*)d_in[4];
    float* out = (float*)d_out;

    k_A<<<CMB + WTB, 256>>>(hidden, W, cb, cc);

    dim3 gB(NH / 256, NB);
    k_scan_combine<<<gB, 256>>>(cb, cc);

    dim3 gC(32, SPLIT);
    k_gemm<<<gC, 288>>>();

    k_red<<<(NCAND * NL + 255) / 256, 256>>>(bias, out);
}

// round 8
// speedup vs baseline: 1.3924x; 1.1099x over previous
#include <cuda_runtime.h>
#include <float.h>

#define NB 32
#define NS 512
#define NH 1024
#define NCAND 256
#define NL 34
#define NLP 36      // labels padded to 9 quads
#define NCH 16      // chunks per sequence
#define CSZ 32      // tokens per chunk
#define SPLIT 8     // K-split (warps per gemm block)
#define KS (2 * NH / SPLIT)   // 256 floats per split
#define CMB 2048    // chunkmax blocks in fused kernel A
#define WTB 288     // wt blocks in fused kernel A (288*256 = 36*2048)

// Scratch (__device__ globals; no allocation allowed)
__device__ float g_cmax[NB * NCH * NH];
__device__ float g_plp[NCAND * NH];
__device__ float g_prp[NCAND * NH];
__device__ float g_pooled[NCAND * 2 * NH];
__device__ float g_Wt[NLP * 2 * NH];             // W transposed+padded [36][2048]

// ---------------------------------------------------------------------------
// Kernel A (fused): chunk maxes + candidate in-chunk partials, AND the W
// transpose as extra trailing blocks (overlaps with the DRAM-bound stream).
// hidden is read exactly once (64 MB).
// ---------------------------------------------------------------------------
__global__ void k_A(const float* __restrict__ hidden,
                    const float* __restrict__ W,
                    const int* __restrict__ cb,
                    const int* __restrict__ cc) {
    int bid = blockIdx.x;
    int tid = threadIdx.x;

    if (bid >= CMB) {   // ---- W transpose part ----
        int idx = (bid - CMB) * 256 + tid;
        int l = idx >> 11;
        int k = idx & (2 * NH - 1);
        g_Wt[idx] = (l < NL) ? W[(size_t)k * NL + l] : 0.f;
        return;
    }

    // ---- chunkmax part: bid = b*64 + q*4 + hblk ----
    __shared__ int s_cnt;
    __shared__ int s_n[NCAND];
    __shared__ int s_r[NCAND];

    int b = bid >> 6;
    int rest = bid & 63;
    int q = rest >> 2;
    int h = (rest & 3) * 256 + tid;

    if (tid == 0) s_cnt = 0;
    __syncthreads();
    {
        int cn = cc[tid];           // tid in [0,256) == NCAND
        if (cb[tid] == b && (cn >> 5) == q) {
            int p = atomicAdd(&s_cnt, 1);
            s_n[p] = tid;
            s_r[p] = cn & 31;
        }
    }

    const float* base = hidden + ((size_t)(b * NS + q * CSZ)) * NH + h;
    float v[CSZ];
#pragma unroll
    for (int k = 0; k < CSZ; k++) v[k] = base[(size_t)k * NH];
    float m = -FLT_MAX;
#pragma unroll
    for (int k = 0; k < CSZ; k++) m = fmaxf(m, v[k]);
    g_cmax[((size_t)b * NCH + q) * NH + h] = m;

    __syncthreads();
    int cnt = s_cnt;
    for (int j = 0; j < cnt; j++) {
        int n = s_n[j];
        int r = s_r[j];
        float ml = -FLT_MAX, mr = -FLT_MAX;
#pragma unroll
        for (int k = 0; k < CSZ; k++) {
            if (k < r) ml = fmaxf(ml, v[k]);
            else       mr = fmaxf(mr, v[k]);
        }
        g_plp[(size_t)n * NH + h] = ml;
        g_prp[(size_t)n * NH + h] = mr;
    }
}

// ---------------------------------------------------------------------------
// Kernel B: prefix/suffix max over chunk maxes, emit pooled per candidate.
// ---------------------------------------------------------------------------
__global__ void k_scan_combine(const int* __restrict__ cb,
                               const int* __restrict__ cc) {
    __shared__ float sh_pref[NCH][256];
    __shared__ float sh_suf[NCH][256];
    __shared__ int s_cnt;
    __shared__ int s_n[NCAND];
    __shared__ int s_q[NCAND];

    int tid = threadIdx.x;
    int h = blockIdx.x * 256 + tid;
    int b = blockIdx.y;

    if (tid == 0) s_cnt = 0;
    __syncthreads();
    if (cb[tid] == b) {
        int p = atomicAdd(&s_cnt, 1);
        s_n[p] = tid;
        s_q[p] = cc[tid] >> 5;
    }

    const float* cm = g_cmax + (size_t)b * NCH * NH + h;
    float v[NCH];
#pragma unroll
    for (int q = 0; q < NCH; q++) v[q] = cm[(size_t)q * NH];

    float run = -FLT_MAX;
#pragma unroll
    for (int q = 0; q < NCH; q++) {
        sh_pref[q][tid] = run;
        run = fmaxf(run, v[q]);
    }
    run = -FLT_MAX;
#pragma unroll
    for (int q = NCH - 1; q >= 0; q--) {
        sh_suf[q][tid] = run;
        run = fmaxf(run, v[q]);
    }
    __syncthreads();

    int cnt = s_cnt;
    for (int j = 0; j < cnt; j++) {
        int n = s_n[j];
        int q = s_q[j];
        float pl = fmaxf(g_plp[(size_t)n * NH + h], sh_pref[q][tid]);
        float pr = fmaxf(g_prp[(size_t)n * NH + h], sh_suf[q][tid]);
        g_pooled[(size_t)n * (2 * NH) + h] = pl;
        g_pooled[(size_t)n * (2 * NH) + NH + h] = pr;
    }
}

// ---------------------------------------------------------------------------
// Kernel C: gemm with fused reduction. Block = (cand-oct, label-quad),
// grid 32x9; the 8 warps are K-splits of the SAME output tile, so the
// K-reduction completes in smem inside the block and writes out directly
// (k_red kernel eliminated). Lane holds 8 A-float4 + 4 W-float4 per step,
// 128 FMA per 12 loads.
// ---------------------------------------------------------------------------
__global__ __launch_bounds__(256) void k_gemm(const float* __restrict__ bias,
                                              float* __restrict__ out) {
    __shared__ float sp[SPLIT][32];
    int wid = threadIdx.x >> 5;     // K-split 0..7
    int lane = threadIdx.x & 31;
    int co = blockIdx.x;            // cand-oct 0..31
    int lq = blockIdx.y;            // label-quad 0..8
    int kbase = wid * KS;

    const float4* A = (const float4*)(g_pooled + (size_t)(co * 8) * (2 * NH) + kbase);
    const float4* Wt = (const float4*)(g_Wt + (size_t)(lq * 4) * (2 * NH) + kbase);
    const int rs = (2 * NH) / 4;    // row stride in float4

    float acc[8][4];
#pragma unroll
    for (int c = 0; c < 8; c++)
#pragma unroll
        for (int l = 0; l < 4; l++) acc[c][l] = 0.f;

#pragma unroll
    for (int step = 0; step < KS / 128; step++) {   // 2 steps
        int i = lane + step * 32;
        float4 a[8], w[4];
#pragma unroll
        for (int c = 0; c < 8; c++) a[c] = A[c * rs + i];
#pragma unroll
        for (int l = 0; l < 4; l++) w[l] = Wt[l * rs + i];
#pragma unroll
        for (int c = 0; c < 8; c++)
#pragma unroll
            for (int l = 0; l < 4; l++) {
                acc[c][l] += a[c].x * w[l].x;
                acc[c][l] += a[c].y * w[l].y;
                acc[c][l] += a[c].z * w[l].z;
                acc[c][l] += a[c].w * w[l].w;
            }
    }

#pragma unroll
    for (int c = 0; c < 8; c++)
#pragma unroll
        for (int l = 0; l < 4; l++) {
            float s = acc[c][l];
#pragma unroll
            for (int o = 16; o; o >>= 1) s += __shfl_xor_sync(0xffffffffu, s, o);
            if (lane == 0) sp[wid][c * 4 + l] = s;
        }
    __syncthreads();

    // 32 outputs per block: thread t -> (c = t>>2, l = t&3).
    if (threadIdx.x < 32) {
        int c = threadIdx.x >> 2;
        int l = threadIdx.x & 3;
        int label = lq * 4 + l;
        if (label < NL) {
            float s = bias[label];
#pragma unroll
            for (int w = 0; w < SPLIT; w++) s += sp[w][threadIdx.x];
            out[(size_t)(co * 8 + c) * NL + label] = s;
        }
    }
}

// ---------------------------------------------------------------------------
extern "C" void kernel_launch(void* const* d_in, const int* in_sizes, int n_in,
                              void* d_out, int out_size) {
    const float* hidden = (const float*)d_in[0];
    const float* W = (const float*)d_in[1];
    const float* bias = (const float*)d_in[2];
    const int* cb = (const int*)d_in[3];
    const int* cc = (const int*)d_in[4];
    float* out = (float*)d_out;

    k_A<<<CMB + WTB, 256>>>(hidden, W, cb, cc);

    dim3 gB(NH / 256, NB);
    k_scan_combine<<<gB, 256>>>(cb, cc);

    dim3 gC(32, 9);
    k_gemm<<<gC, 256>>>(bias, out);
}